// round 12
// baseline (speedup 1.0000x reference)
#include <cuda_runtime.h>
#include <math.h>

// Problem constants
#define TT    1024
#define DIMX  1024
#define HH    8
#define DK    192
#define DV    128
#define QLR   768
#define KVLR  512
#define DROPE 64

// Stage-1 concatenated layout (columns of big buffer):
//   [0,768) qa | [768,1344) kva (k_pe at 1280) | [1344,2880) eg | [2880,2888) beta | pad
#define NBIG 2944

// ---------------- scratch ----------------
__device__ float d_bc  [DIMX * NBIG];
__device__ float d_big [TT * NBIG];
__device__ float d_qn  [TT * QLR];
__device__ float d_kvn [TT * KVLR];
__device__ float d_q   [TT * HH * DK];
__device__ float d_kv  [TT * HH * 256];
__device__ float d_kf  [TT * HH * DK];
__device__ float d_qk  [TT * HH];
__device__ float d_ov  [TT * HH * DV];

// ================= TF32 tensor-core GEMM (double-buffered, cp.async B) =================
#define BM 64
#define BN 128
#define BK 16

__device__ __forceinline__ unsigned f2tf(float f) {
    unsigned u;
    asm("cvt.rna.tf32.f32 %0, %1;" : "=r"(u) : "f"(f));
    return u;
}

__device__ __forceinline__ void mma_tf32(float* c, const unsigned* a, const unsigned* b) {
    asm volatile(
        "mma.sync.aligned.m16n8k8.row.col.f32.tf32.tf32.f32 "
        "{%0,%1,%2,%3}, {%4,%5,%6,%7}, {%8,%9}, {%0,%1,%2,%3};\n"
        : "+f"(c[0]), "+f"(c[1]), "+f"(c[2]), "+f"(c[3])
        : "r"(a[0]), "r"(a[1]), "r"(a[2]), "r"(a[3]), "r"(b[0]), "r"(b[1]));
}

__device__ __forceinline__ void cp16(float* dst, const float* src) {
    unsigned s = (unsigned)__cvta_generic_to_shared(dst);
    asm volatile("cp.async.ca.shared.global [%0], [%1], 16;\n" :: "r"(s), "l"(src));
}
#define CP_COMMIT() asm volatile("cp.async.commit_group;\n" ::: "memory")
#define CP_WAIT0()  asm volatile("cp.async.wait_group 0;\n" ::: "memory")

// EPI: 0 none, 1 = stage-1 epilogue (sigmoid for g/beta column ranges)
__device__ __forceinline__ float epi1(float v, int gc, const float* __restrict__ bias) {
    if (gc >= 1344 && gc < 2888) {
        float b = (gc < 2880) ? bias[gc - 1344] : 0.f;
        v = 1.f / (1.f + expf(-(v + b)));
    }
    return v;
}

// smem raw fp32 (A transposed+swizzled, B swizzled); cvt.rna.tf32 at fragment load.
template <int EPI>
__device__ __forceinline__ void tgemm_core(int N, int K,
                                           const float* __restrict__ A, int lda,
                                           const float* __restrict__ B, int ldb,
                                           const float* __restrict__ bias,
                                           float* __restrict__ C, int ldc,
                                           float* sA, float* sB) {
    const int tid  = threadIdx.x;             // 256 threads = 8 warps
    const int crow = blockIdx.y * BM;
    const int ccol = blockIdx.x * BN;

    const int wid  = tid >> 5;
    const int lane = tid & 31;
    const int lq   = lane >> 2;
    const int lr   = lane & 3;
    const int rm   = (wid & 1) * 32;   // 2 warps in M
    const int cn   = (wid >> 1) * 32;  // 4 warps in N

    const int am  = tid >> 2;          // 0..63
    const int ak4 = (tid & 3) * 4;     // 0,4,8,12
    const int bk  = tid >> 4;          // 0..15
    const int bc8 = (tid & 15) * 8;    // 0..120
    const int swb = (((bk & 3) ^ ((bk >> 2) & 3)) << 3);

    float acc[2][4][4] = {};
    float4 aR;

    // ---- prologue: tile 0 ----
    aR = *reinterpret_cast<const float4*>(&A[(long)(crow + am) * lda + ak4]);
    cp16(&sB[bk * BN + ((bc8) ^ swb)],     &B[(long)bk * ldb + ccol + bc8]);
    cp16(&sB[bk * BN + ((bc8 + 4) ^ swb)], &B[(long)bk * ldb + ccol + bc8 + 4]);
    CP_COMMIT();
    {
        const float av[4] = {aR.x, aR.y, aR.z, aR.w};
        #pragma unroll
        for (int i = 0; i < 4; ++i) {
            const int k  = ak4 + i;
            const int sw = (((k & 3) ^ ((k >> 2) & 3)) << 3);
            sA[k * BM + (am ^ sw)] = av[i];
        }
    }
    if (K > BK)
        aR = *reinterpret_cast<const float4*>(&A[(long)(crow + am) * lda + BK + ak4]);
    CP_WAIT0();
    __syncthreads();

    int buf = 0;
    for (int k0 = 0; k0 < K; k0 += BK, buf ^= 1) {
        float* cA = sA + buf * (BK * BM);
        float* cB = sB + buf * (BK * BN);
        const int nxt = buf ^ 1;

        // ---- issue next tile into the other buffer ----
        if (k0 + BK < K) {
            float* nB = sB + nxt * (BK * BN);
            cp16(&nB[bk * BN + ((bc8) ^ swb)],     &B[(long)(k0 + BK + bk) * ldb + ccol + bc8]);
            cp16(&nB[bk * BN + ((bc8 + 4) ^ swb)], &B[(long)(k0 + BK + bk) * ldb + ccol + bc8 + 4]);
            CP_COMMIT();
            float* nA = sA + nxt * (BK * BM);
            const float av[4] = {aR.x, aR.y, aR.z, aR.w};
            #pragma unroll
            for (int i = 0; i < 4; ++i) {
                const int k  = ak4 + i;
                const int sw = (((k & 3) ^ ((k >> 2) & 3)) << 3);
                nA[k * BM + (am ^ sw)] = av[i];
            }
            if (k0 + 2 * BK < K)
                aR = *reinterpret_cast<const float4*>(&A[(long)(crow + am) * lda + k0 + 2 * BK + ak4]);
        }

        // ---- compute on current buffer ----
        #pragma unroll
        for (int k8 = 0; k8 < BK; k8 += 8) {
            const int f0 = ((lr ^ (k8 >> 2)) & 3) << 3;
            const int f1 = f0 ^ 8;
            unsigned af[2][4], bf[4][2];
            #pragma unroll
            for (int mt = 0; mt < 2; ++mt) {
                const int r = rm + mt * 16 + lq;
                af[mt][0] = f2tf(cA[(k8 + lr) * BM + (r ^ f0)]);
                af[mt][1] = f2tf(cA[(k8 + lr) * BM + ((r + 8) ^ f0)]);
                af[mt][2] = f2tf(cA[(k8 + lr + 4) * BM + (r ^ f1)]);
                af[mt][3] = f2tf(cA[(k8 + lr + 4) * BM + ((r + 8) ^ f1)]);
            }
            #pragma unroll
            for (int nt = 0; nt < 4; ++nt) {
                const int c = cn + nt * 8 + lq;
                bf[nt][0] = f2tf(cB[(k8 + lr) * BN + (c ^ f0)]);
                bf[nt][1] = f2tf(cB[(k8 + lr + 4) * BN + (c ^ f1)]);
            }
            #pragma unroll
            for (int mt = 0; mt < 2; ++mt)
                #pragma unroll
                for (int nt = 0; nt < 4; ++nt)
                    mma_tf32(acc[mt][nt], af[mt], bf[nt]);
        }
        CP_WAIT0();
        __syncthreads();
    }

    #pragma unroll
    for (int mt = 0; mt < 2; ++mt) {
        const int row = crow + rm + mt * 16 + lq;
        #pragma unroll
        for (int nt = 0; nt < 4; ++nt) {
            const int col = ccol + cn + nt * 8 + lr * 2;
            float v0 = acc[mt][nt][0], v1 = acc[mt][nt][1];
            float v2 = acc[mt][nt][2], v3 = acc[mt][nt][3];
            if (EPI == 1) {
                v0 = epi1(v0, col, bias);     v1 = epi1(v1, col + 1, bias);
                v2 = epi1(v2, col, bias);     v3 = epi1(v3, col + 1, bias);
            }
            *reinterpret_cast<float2*>(&C[(long)row * ldc + col])       = make_float2(v0, v1);
            *reinterpret_cast<float2*>(&C[(long)(row + 8) * ldc + col]) = make_float2(v2, v3);
        }
    }
}

template <int EPI>
__global__ __launch_bounds__(256, 2)
void tgemm_kernel(int N, int K, const float* __restrict__ A, int lda,
                  const float* __restrict__ B, int ldb,
                  const float* __restrict__ bias, float* __restrict__ C, int ldc) {
    __shared__ float sA[2 * BK * BM];
    __shared__ float sB[2 * BK * BN];
    tgemm_core<EPI>(N, K, A, lda, B, ldb, bias, C, ldc, sA, sB);
}

__global__ __launch_bounds__(256, 2)
void tgemm_dual_kernel(int N0, int K0, const float* __restrict__ A0,
                       const float* __restrict__ B0, float* __restrict__ C0,
                       int N1, int K1, const float* __restrict__ A1,
                       const float* __restrict__ B1, float* __restrict__ C1) {
    __shared__ float sA[2 * BK * BM];
    __shared__ float sB[2 * BK * BN];
    if (blockIdx.z == 0) {
        if ((int)blockIdx.x * BN >= N0) return;
        tgemm_core<0>(N0, K0, A0, K0, B0, N0, nullptr, C0, N0, sA, sB);
    } else {
        tgemm_core<0>(N1, K1, A1, K1, B1, N1, nullptr, C1, N1, sA, sB);
    }
}

// ---------------- stage-1 weight concat ----------------
__global__ void concat_w(const float* __restrict__ wq_a,
                         const float* __restrict__ wkv_a,
                         const float* __restrict__ wg_w,
                         const float* __restrict__ wb,
                         float* __restrict__ Bc) {
    const int c = blockIdx.x * 128 + threadIdx.x;
    const int r = blockIdx.y;
    float v;
    if      (c < 768)  v = wq_a [r * 768  + c];
    else if (c < 1344) v = wkv_a[r * 576  + (c - 768)];
    else if (c < 2880) v = wg_w [r * 1536 + (c - 1344)];
    else if (c < 2888) v = wb   [r * 8    + (c - 2880)];
    else               v = 0.f;
    Bc[(long)r * NBIG + c] = v;
}

// ---------------- fused row RMS norms (q then kv) ----------------
__device__ __forceinline__ void rms_row(const float* __restrict__ row,
                                        const float* __restrict__ w,
                                        float* __restrict__ out, int n) {
    float ss = 0.f;
    for (int i = threadIdx.x; i < n; i += 256) {
        float v = row[i];
        ss += v * v;
    }
    #pragma unroll
    for (int off = 16; off; off >>= 1)
        ss += __shfl_xor_sync(0xffffffffu, ss, off);
    __shared__ float red[8];
    __shared__ float scale_s;
    const int wid = threadIdx.x >> 5;
    if ((threadIdx.x & 31) == 0) red[wid] = ss;
    __syncthreads();
    if (threadIdx.x == 0) {
        float tot = 0.f;
        #pragma unroll
        for (int i = 0; i < 8; ++i) tot += red[i];
        scale_s = rsqrtf(tot / (float)n + 1e-5f);
    }
    __syncthreads();
    const float sc = scale_s;
    for (int i = threadIdx.x; i < n; i += 256)
        out[i] = row[i] * sc * w[i];
    __syncthreads();   // shared red/scale reused by second call
}

__global__ void rms_fused(const float* __restrict__ big,
                          const float* __restrict__ qw,
                          const float* __restrict__ kvw,
                          float* __restrict__ qn,
                          float* __restrict__ kvn) {
    const int t = blockIdx.x;
    rms_row(big + (long)t * NBIG,       qw,  qn  + (long)t * QLR,  QLR);
    rms_row(big + (long)t * NBIG + 768, kvw, kvn + (long)t * KVLR, KVLR);
}

// ---------------- prep: l2norm q/k, assemble k, precompute qk = q.k ----------------
__global__ void prep_kernel(float* __restrict__ q,
                            const float* __restrict__ kv,
                            const float* __restrict__ big,
                            float* __restrict__ kf,
                            float* __restrict__ qkb) {
    const int t = blockIdx.x >> 3;
    const int h = blockIdx.x & 7;
    const int i = threadIdx.x;  // 0..191

    const int qidx = t * (HH * DK) + h * DK + i;
    const float qv = q[qidx];
    const float kvv = (i < 128) ? kv[t * (HH * 256) + h * 256 + i]
                                : big[(long)t * NBIG + 1280 + (i - 128)];

    float q2 = qv * qv, k2 = kvv * kvv;
    #pragma unroll
    for (int off = 16; off; off >>= 1) {
        q2 += __shfl_xor_sync(0xffffffffu, q2, off);
        k2 += __shfl_xor_sync(0xffffffffu, k2, off);
    }
    __shared__ float sq[6], sk[6], sp[6];
    __shared__ float scl[2];
    const int wid = threadIdx.x >> 5;
    if ((threadIdx.x & 31) == 0) { sq[wid] = q2; sk[wid] = k2; }
    __syncthreads();
    if (threadIdx.x == 0) {
        float a = 0.f, b = 0.f;
        #pragma unroll
        for (int j = 0; j < 6; ++j) { a += sq[j]; b += sk[j]; }
        scl[0] = rsqrtf(a + 1e-6f) * 0.07216878364870322f;
        scl[1] = rsqrtf(b + 1e-6f);
    }
    __syncthreads();
    const float qo = qv * scl[0];
    const float ko = kvv * scl[1];
    q[qidx] = qo;
    kf[qidx] = ko;

    // qk = sum(qo * ko) over the 192 dims
    float p = qo * ko;
    #pragma unroll
    for (int off = 16; off; off >>= 1)
        p += __shfl_xor_sync(0xffffffffu, p, off);
    if ((threadIdx.x & 31) == 0) sp[wid] = p;
    __syncthreads();
    if (threadIdx.x == 0) {
        float tot = 0.f;
        #pragma unroll
        for (int j = 0; j < 6; ++j) tot += sp[j];
        qkb[t * HH + h] = tot;
    }
}

// ---------------- KDA recurrence: 16-lane groups, 2 v per warp, qk precomputed ----
// warp = h*64 + pair; lane&15 owns k = (lane&15)*12..+11; lane>>4 selects v = pair*2 + (lane>>4).
// Reductions: 4-level shfl_xor butterfly (8,4,2,1) within 16-lane groups. 8 shfls/step for 2 v.
struct RecIn {
    float e[12], k[12], q[12];
    float vt, bt, qk;
};

__global__ __launch_bounds__(64)
void kda_rec(const float* __restrict__ qf,    // [T, 1536]
             const float* __restrict__ kf,    // [T, 1536]
             const float* __restrict__ big,   // eg at 1344, beta at 2880
             const float* __restrict__ kv,    // [T, 2048], v at h*256+128
             const float* __restrict__ qkb,   // [T, 8]
             float* __restrict__ o) {         // [T, 1024]
    const int warp  = (blockIdx.x << 1) + (threadIdx.x >> 5);  // 0..511
    const int lane  = threadIdx.x & 31;
    const int h     = warp >> 6;          // 0..7
    const int pair  = warp & 63;          // 0..63
    const int kslot = lane & 15;          // k-slice
    const int v     = pair * 2 + (lane >> 4);
    const int kbase = h * DK + kslot * 12;

    float s[12];
    #pragma unroll
    for (int i = 0; i < 12; ++i) s[i] = 0.f;

    #define RLOAD(I, tt) do {                                                    \
        const int _t = (tt) & (TT - 1);                                          \
        const float4* e4 = (const float4*)(big + (long)_t * NBIG + 1344 + kbase);\
        const float4* k4 = (const float4*)(kf + (long)_t * 1536 + kbase);        \
        const float4* q4 = (const float4*)(qf + (long)_t * 1536 + kbase);        \
        _Pragma("unroll")                                                        \
        for (int j = 0; j < 3; ++j) {                                            \
            float4 te = e4[j], tk = k4[j], tq = q4[j];                           \
            (I).e[j*4+0] = te.x; (I).e[j*4+1] = te.y; (I).e[j*4+2] = te.z; (I).e[j*4+3] = te.w; \
            (I).k[j*4+0] = tk.x; (I).k[j*4+1] = tk.y; (I).k[j*4+2] = tk.z; (I).k[j*4+3] = tk.w; \
            (I).q[j*4+0] = tq.x; (I).q[j*4+1] = tq.y; (I).q[j*4+2] = tq.z; (I).q[j*4+3] = tq.w; \
        }                                                                        \
        (I).vt = kv[_t * 2048 + h * 256 + 128 + v];                              \
        (I).bt = big[(long)_t * NBIG + 2880 + h];                                \
        (I).qk = qkb[_t * HH + h];                                               \
    } while (0)

    #define DOT12(res, a, b) do {                                                \
        float t0 = fmaf((a)[0], (b)[0], (a)[1] * (b)[1]);                        \
        float t1 = fmaf((a)[2], (b)[2], (a)[3] * (b)[3]);                        \
        float t2 = fmaf((a)[4], (b)[4], (a)[5] * (b)[5]);                        \
        float t3 = fmaf((a)[6], (b)[6], (a)[7] * (b)[7]);                        \
        float t4 = fmaf((a)[8], (b)[8], (a)[9] * (b)[9]);                        \
        float t5 = fmaf((a)[10], (b)[10], (a)[11] * (b)[11]);                    \
        (res) = ((t0 + t1) + (t2 + t3)) + (t4 + t5);                             \
    } while (0)

    #define RSTEP(I, t) do {                                                     \
        _Pragma("unroll")                                                        \
        for (int i = 0; i < 12; ++i) s[i] *= (I).e[i];                           \
        float kse, qse;                                                          \
        DOT12(kse, s, (I).k);                                                    \
        DOT12(qse, s, (I).q);                                                    \
        _Pragma("unroll")                                                        \
        for (int off = 8; off; off >>= 1) {                                      \
            kse += __shfl_xor_sync(0xffffffffu, kse, off);                       \
            qse += __shfl_xor_sync(0xffffffffu, qse, off);                       \
        }                                                                        \
        const float u = (I).bt * ((I).vt - kse);                                 \
        float ov = fmaf((I).qk, u, qse);                                         \
        _Pragma("unroll")                                                        \
        for (int i = 0; i < 12; ++i) s[i] = fmaf((I).k[i], u, s[i]);             \
        if (kslot == 0) {                                                        \
            if (ov != ov) ov = 0.f;                                              \
            ov = fminf(fmaxf(ov, -10000.f), 10000.f);                            \
            o[(t) * (HH * DV) + h * DV + v] = ov;                                \
        }                                                                        \
    } while (0)

    RecIn ia, ib;
    RLOAD(ia, 0);
    for (int t = 0; t < TT; t += 2) {
        RLOAD(ib, t + 1);
        RSTEP(ia, t);
        RLOAD(ia, t + 2);
        RSTEP(ib, t + 1);
    }
    #undef RLOAD
    #undef DOT12
    #undef RSTEP
}

// ---------------- launch ----------------
extern "C" void kernel_launch(void* const* d_in, const int* in_sizes, int n_in,
                              void* d_out, int out_size) {
    (void)in_sizes; (void)n_in; (void)out_size;
    const float* x         = (const float*)d_in[0];
    const float* wq_a      = (const float*)d_in[3];
    const float* q_norm_w  = (const float*)d_in[4];
    const float* wq_b      = (const float*)d_in[5];
    const float* wkv_a     = (const float*)d_in[6];
    const float* kv_norm_w = (const float*)d_in[7];
    const float* wkv_b     = (const float*)d_in[8];
    const float* wg_w      = (const float*)d_in[9];
    const float* wg_b      = (const float*)d_in[10];
    const float* wb        = (const float*)d_in[11];
    const float* wo        = (const float*)d_in[12];
    float* out = (float*)d_out;

    float *bc, *big, *qn, *kvn, *q, *kv, *kf, *qkb, *ov;
    cudaGetSymbolAddress((void**)&bc,  d_bc);
    cudaGetSymbolAddress((void**)&big, d_big);
    cudaGetSymbolAddress((void**)&qn,  d_qn);
    cudaGetSymbolAddress((void**)&kvn, d_kvn);
    cudaGetSymbolAddress((void**)&q,   d_q);
    cudaGetSymbolAddress((void**)&kv,  d_kv);
    cudaGetSymbolAddress((void**)&kf,  d_kf);
    cudaGetSymbolAddress((void**)&qkb, d_qk);
    cudaGetSymbolAddress((void**)&ov,  d_ov);

    concat_w<<<dim3(NBIG / 128, DIMX), 128>>>(wq_a, wkv_a, wg_w, wb, bc);

    // Stage 1: big = x @ [wq_a | wkv_a | wg_w | wb] (+ sigmoid epilogues)
    tgemm_kernel<1><<<dim3(NBIG / BN, TT / BM), 256>>>(NBIG, DIMX, x, DIMX, bc, NBIG, wg_b, big, NBIG);

    // Stage 2: fused RMS norms
    rms_fused<<<TT, 256>>>(big, q_norm_w, kv_norm_w, qn, kvn);

    // Stage 3: batched up-projections
    tgemm_dual_kernel<<<dim3(2048 / BN, TT / BM, 2), 256>>>(
        1536, QLR,  qn,  wq_b,  q,
        2048, KVLR, kvn, wkv_b, kv);

    // Stage 4: l2norm q/k, assemble k, precompute qk
    prep_kernel<<<TT * HH, 192>>>(q, kv, big, kf, qkb);

    // Stage 5: sequential KDA recurrence (16-lane groups, 2 v/warp)
    kda_rec<<<256, 64>>>(q, kf, big, kv, qkb, ov);

    // Stage 6: output projection (plain TF32)
    tgemm_kernel<0><<<dim3(DIMX / BN, TT / BM), 256>>>(DIMX, DIMX, ov, DIMX, wo, DIMX, nullptr, out, DIMX);
}

// round 13
// speedup vs baseline: 1.3351x; 1.3351x over previous
#include <cuda_runtime.h>
#include <math.h>

// Problem constants
#define TT    1024
#define DIMX  1024
#define HH    8
#define DK    192
#define DV    128
#define QLR   768
#define KVLR  512
#define DROPE 64

// Stage-1 concatenated layout (columns of big buffer):
//   [0,768) qa | [768,1344) kva (k_pe at 1280) | [1344,2880) eg | [2880,2888) beta | pad
#define NBIG 2944

// ---------------- scratch ----------------
__device__ float d_bc  [DIMX * NBIG];
__device__ float d_big [TT * NBIG];
__device__ float d_qn  [TT * QLR];
__device__ float d_kvn [TT * KVLR];
__device__ float d_q   [TT * HH * DK];
__device__ float d_kv  [TT * HH * 256];
__device__ float d_kf  [TT * HH * DK];
__device__ float d_qk  [TT * HH];
__device__ float d_ov  [TT * HH * DV];

// ================= TF32 tensor-core GEMM (double-buffered, cp.async B) =================
#define BM 64
#define BN 128
#define BK 16

__device__ __forceinline__ unsigned f2tf(float f) {
    unsigned u;
    asm("cvt.rna.tf32.f32 %0, %1;" : "=r"(u) : "f"(f));
    return u;
}

__device__ __forceinline__ void mma_tf32(float* c, const unsigned* a, const unsigned* b) {
    asm volatile(
        "mma.sync.aligned.m16n8k8.row.col.f32.tf32.tf32.f32 "
        "{%0,%1,%2,%3}, {%4,%5,%6,%7}, {%8,%9}, {%0,%1,%2,%3};\n"
        : "+f"(c[0]), "+f"(c[1]), "+f"(c[2]), "+f"(c[3])
        : "r"(a[0]), "r"(a[1]), "r"(a[2]), "r"(a[3]), "r"(b[0]), "r"(b[1]));
}

__device__ __forceinline__ void cp16(float* dst, const float* src) {
    unsigned s = (unsigned)__cvta_generic_to_shared(dst);
    asm volatile("cp.async.ca.shared.global [%0], [%1], 16;\n" :: "r"(s), "l"(src));
}
#define CP_COMMIT() asm volatile("cp.async.commit_group;\n" ::: "memory")
#define CP_WAIT0()  asm volatile("cp.async.wait_group 0;\n" ::: "memory")

// EPI: 0 none, 1 = stage-1 epilogue (sigmoid for g/beta column ranges)
__device__ __forceinline__ float epi1(float v, int gc, const float* __restrict__ bias) {
    if (gc >= 1344 && gc < 2888) {
        float b = (gc < 2880) ? bias[gc - 1344] : 0.f;
        v = 1.f / (1.f + expf(-(v + b)));
    }
    return v;
}

// smem raw fp32 (A transposed+swizzled, B swizzled); cvt.rna.tf32 at fragment load.
template <int EPI>
__device__ __forceinline__ void tgemm_core(int N, int K,
                                           const float* __restrict__ A, int lda,
                                           const float* __restrict__ B, int ldb,
                                           const float* __restrict__ bias,
                                           float* __restrict__ C, int ldc,
                                           float* sA, float* sB) {
    const int tid  = threadIdx.x;             // 256 threads = 8 warps
    const int crow = blockIdx.y * BM;
    const int ccol = blockIdx.x * BN;

    const int wid  = tid >> 5;
    const int lane = tid & 31;
    const int lq   = lane >> 2;
    const int lr   = lane & 3;
    const int rm   = (wid & 1) * 32;   // 2 warps in M
    const int cn   = (wid >> 1) * 32;  // 4 warps in N

    const int am  = tid >> 2;          // 0..63
    const int ak4 = (tid & 3) * 4;     // 0,4,8,12
    const int bk  = tid >> 4;          // 0..15
    const int bc8 = (tid & 15) * 8;    // 0..120
    const int swb = (((bk & 3) ^ ((bk >> 2) & 3)) << 3);

    float acc[2][4][4] = {};
    float4 aR;

    // ---- prologue: tile 0 ----
    aR = *reinterpret_cast<const float4*>(&A[(long)(crow + am) * lda + ak4]);
    cp16(&sB[bk * BN + ((bc8) ^ swb)],     &B[(long)bk * ldb + ccol + bc8]);
    cp16(&sB[bk * BN + ((bc8 + 4) ^ swb)], &B[(long)bk * ldb + ccol + bc8 + 4]);
    CP_COMMIT();
    {
        const float av[4] = {aR.x, aR.y, aR.z, aR.w};
        #pragma unroll
        for (int i = 0; i < 4; ++i) {
            const int k  = ak4 + i;
            const int sw = (((k & 3) ^ ((k >> 2) & 3)) << 3);
            sA[k * BM + (am ^ sw)] = av[i];
        }
    }
    if (K > BK)
        aR = *reinterpret_cast<const float4*>(&A[(long)(crow + am) * lda + BK + ak4]);
    CP_WAIT0();
    __syncthreads();

    int buf = 0;
    for (int k0 = 0; k0 < K; k0 += BK, buf ^= 1) {
        float* cA = sA + buf * (BK * BM);
        float* cB = sB + buf * (BK * BN);
        const int nxt = buf ^ 1;

        // ---- issue next tile into the other buffer ----
        if (k0 + BK < K) {
            float* nB = sB + nxt * (BK * BN);
            cp16(&nB[bk * BN + ((bc8) ^ swb)],     &B[(long)(k0 + BK + bk) * ldb + ccol + bc8]);
            cp16(&nB[bk * BN + ((bc8 + 4) ^ swb)], &B[(long)(k0 + BK + bk) * ldb + ccol + bc8 + 4]);
            CP_COMMIT();
            float* nA = sA + nxt * (BK * BM);
            const float av[4] = {aR.x, aR.y, aR.z, aR.w};
            #pragma unroll
            for (int i = 0; i < 4; ++i) {
                const int k  = ak4 + i;
                const int sw = (((k & 3) ^ ((k >> 2) & 3)) << 3);
                nA[k * BM + (am ^ sw)] = av[i];
            }
            if (k0 + 2 * BK < K)
                aR = *reinterpret_cast<const float4*>(&A[(long)(crow + am) * lda + k0 + 2 * BK + ak4]);
        }

        // ---- compute on current buffer ----
        #pragma unroll
        for (int k8 = 0; k8 < BK; k8 += 8) {
            const int f0 = ((lr ^ (k8 >> 2)) & 3) << 3;
            const int f1 = f0 ^ 8;
            unsigned af[2][4], bf[4][2];
            #pragma unroll
            for (int mt = 0; mt < 2; ++mt) {
                const int r = rm + mt * 16 + lq;
                af[mt][0] = f2tf(cA[(k8 + lr) * BM + (r ^ f0)]);
                af[mt][1] = f2tf(cA[(k8 + lr) * BM + ((r + 8) ^ f0)]);
                af[mt][2] = f2tf(cA[(k8 + lr + 4) * BM + (r ^ f1)]);
                af[mt][3] = f2tf(cA[(k8 + lr + 4) * BM + ((r + 8) ^ f1)]);
            }
            #pragma unroll
            for (int nt = 0; nt < 4; ++nt) {
                const int c = cn + nt * 8 + lq;
                bf[nt][0] = f2tf(cB[(k8 + lr) * BN + (c ^ f0)]);
                bf[nt][1] = f2tf(cB[(k8 + lr + 4) * BN + (c ^ f1)]);
            }
            #pragma unroll
            for (int mt = 0; mt < 2; ++mt)
                #pragma unroll
                for (int nt = 0; nt < 4; ++nt)
                    mma_tf32(acc[mt][nt], af[mt], bf[nt]);
        }
        CP_WAIT0();
        __syncthreads();
    }

    #pragma unroll
    for (int mt = 0; mt < 2; ++mt) {
        const int row = crow + rm + mt * 16 + lq;
        #pragma unroll
        for (int nt = 0; nt < 4; ++nt) {
            const int col = ccol + cn + nt * 8 + lr * 2;
            float v0 = acc[mt][nt][0], v1 = acc[mt][nt][1];
            float v2 = acc[mt][nt][2], v3 = acc[mt][nt][3];
            if (EPI == 1) {
                v0 = epi1(v0, col, bias);     v1 = epi1(v1, col + 1, bias);
                v2 = epi1(v2, col, bias);     v3 = epi1(v3, col + 1, bias);
            }
            *reinterpret_cast<float2*>(&C[(long)row * ldc + col])       = make_float2(v0, v1);
            *reinterpret_cast<float2*>(&C[(long)(row + 8) * ldc + col]) = make_float2(v2, v3);
        }
    }
}

template <int EPI>
__global__ __launch_bounds__(256, 2)
void tgemm_kernel(int N, int K, const float* __restrict__ A, int lda,
                  const float* __restrict__ B, int ldb,
                  const float* __restrict__ bias, float* __restrict__ C, int ldc) {
    __shared__ float sA[2 * BK * BM];
    __shared__ float sB[2 * BK * BN];
    tgemm_core<EPI>(N, K, A, lda, B, ldb, bias, C, ldc, sA, sB);
}

__global__ __launch_bounds__(256, 2)
void tgemm_dual_kernel(int N0, int K0, const float* __restrict__ A0,
                       const float* __restrict__ B0, float* __restrict__ C0,
                       int N1, int K1, const float* __restrict__ A1,
                       const float* __restrict__ B1, float* __restrict__ C1) {
    __shared__ float sA[2 * BK * BM];
    __shared__ float sB[2 * BK * BN];
    if (blockIdx.z == 0) {
        if ((int)blockIdx.x * BN >= N0) return;
        tgemm_core<0>(N0, K0, A0, K0, B0, N0, nullptr, C0, N0, sA, sB);
    } else {
        tgemm_core<0>(N1, K1, A1, K1, B1, N1, nullptr, C1, N1, sA, sB);
    }
}

// ---------------- stage-1 weight concat ----------------
__global__ void concat_w(const float* __restrict__ wq_a,
                         const float* __restrict__ wkv_a,
                         const float* __restrict__ wg_w,
                         const float* __restrict__ wb,
                         float* __restrict__ Bc) {
    const int c = blockIdx.x * 128 + threadIdx.x;
    const int r = blockIdx.y;
    float v;
    if      (c < 768)  v = wq_a [r * 768  + c];
    else if (c < 1344) v = wkv_a[r * 576  + (c - 768)];
    else if (c < 2880) v = wg_w [r * 1536 + (c - 1344)];
    else if (c < 2888) v = wb   [r * 8    + (c - 2880)];
    else               v = 0.f;
    Bc[(long)r * NBIG + c] = v;
}

// ---------------- fused row RMS norms (q then kv) ----------------
__device__ __forceinline__ void rms_row(const float* __restrict__ row,
                                        const float* __restrict__ w,
                                        float* __restrict__ out, int n) {
    float ss = 0.f;
    for (int i = threadIdx.x; i < n; i += 256) {
        float v = row[i];
        ss += v * v;
    }
    #pragma unroll
    for (int off = 16; off; off >>= 1)
        ss += __shfl_xor_sync(0xffffffffu, ss, off);
    __shared__ float red[8];
    __shared__ float scale_s;
    const int wid = threadIdx.x >> 5;
    if ((threadIdx.x & 31) == 0) red[wid] = ss;
    __syncthreads();
    if (threadIdx.x == 0) {
        float tot = 0.f;
        #pragma unroll
        for (int i = 0; i < 8; ++i) tot += red[i];
        scale_s = rsqrtf(tot / (float)n + 1e-5f);
    }
    __syncthreads();
    const float sc = scale_s;
    for (int i = threadIdx.x; i < n; i += 256)
        out[i] = row[i] * sc * w[i];
    __syncthreads();   // shared red/scale reused by second call
}

__global__ void rms_fused(const float* __restrict__ big,
                          const float* __restrict__ qw,
                          const float* __restrict__ kvw,
                          float* __restrict__ qn,
                          float* __restrict__ kvn) {
    const int t = blockIdx.x;
    rms_row(big + (long)t * NBIG,       qw,  qn  + (long)t * QLR,  QLR);
    rms_row(big + (long)t * NBIG + 768, kvw, kvn + (long)t * KVLR, KVLR);
}

// ---------------- prep: l2norm q/k, assemble k, precompute qk = q.k ----------------
__global__ void prep_kernel(float* __restrict__ q,
                            const float* __restrict__ kv,
                            const float* __restrict__ big,
                            float* __restrict__ kf,
                            float* __restrict__ qkb) {
    const int t = blockIdx.x >> 3;
    const int h = blockIdx.x & 7;
    const int i = threadIdx.x;  // 0..191

    const int qidx = t * (HH * DK) + h * DK + i;
    const float qv = q[qidx];
    const float kvv = (i < 128) ? kv[t * (HH * 256) + h * 256 + i]
                                : big[(long)t * NBIG + 1280 + (i - 128)];

    float q2 = qv * qv, k2 = kvv * kvv;
    #pragma unroll
    for (int off = 16; off; off >>= 1) {
        q2 += __shfl_xor_sync(0xffffffffu, q2, off);
        k2 += __shfl_xor_sync(0xffffffffu, k2, off);
    }
    __shared__ float sq[6], sk[6], sp[6];
    __shared__ float scl[2];
    const int wid = threadIdx.x >> 5;
    if ((threadIdx.x & 31) == 0) { sq[wid] = q2; sk[wid] = k2; }
    __syncthreads();
    if (threadIdx.x == 0) {
        float a = 0.f, b = 0.f;
        #pragma unroll
        for (int j = 0; j < 6; ++j) { a += sq[j]; b += sk[j]; }
        scl[0] = rsqrtf(a + 1e-6f) * 0.07216878364870322f;
        scl[1] = rsqrtf(b + 1e-6f);
    }
    __syncthreads();
    const float qo = qv * scl[0];
    const float ko = kvv * scl[1];
    q[qidx] = qo;
    kf[qidx] = ko;

    // qk = sum(qo * ko) over the 192 dims
    float p = qo * ko;
    #pragma unroll
    for (int off = 16; off; off >>= 1)
        p += __shfl_xor_sync(0xffffffffu, p, off);
    if ((threadIdx.x & 31) == 0) sp[wid] = p;
    __syncthreads();
    if (threadIdx.x == 0) {
        float tot = 0.f;
        #pragma unroll
        for (int j = 0; j < 6; ++j) tot += sp[j];
        qkb[t * HH + h] = tot;
    }
}

// ---------------- KDA recurrence: warp per (h,v), dist-3 prefetch, qk precomputed ----
// Two butterflies per step (kse on critical path, qse off-path); qk from prep.
struct RecIn {
    float2 e0, e1, e2, k0, k1, k2, q0, q1, q2;
    float vt, bt, qk;
};

__global__ __launch_bounds__(256)
void kda_rec(const float* __restrict__ qf,
             const float* __restrict__ kf,
             const float* __restrict__ big,
             const float* __restrict__ kv,
             const float* __restrict__ qkb,
             float* __restrict__ o) {
    const int warp = (blockIdx.x * blockDim.x + threadIdx.x) >> 5;  // 0..1023
    const int lane = threadIdx.x & 31;
    const int h = warp >> 7;
    const int v = warp & 127;

    float s0 = 0.f, s1 = 0.f, s2 = 0.f, s3 = 0.f, s4 = 0.f, s5 = 0.f;
    const int kbase = h * DK + lane * 6;

    // loads wrap via &1023 past the sequence end; those buffers are never stepped.
    #define RLOAD(I, tt) do {                                                  \
        const int _t = (tt) & (TT - 1);                                        \
        const int rb = _t * (HH * DK) + kbase;                                 \
        const float* ep = big + (long)_t * NBIG + 1344 + kbase;                \
        (I).e0 = *(const float2*)(ep);     (I).e1 = *(const float2*)(ep + 2);  \
        (I).e2 = *(const float2*)(ep + 4);                                     \
        (I).k0 = *(const float2*)(kf + rb);     (I).k1 = *(const float2*)(kf + rb + 2); \
        (I).k2 = *(const float2*)(kf + rb + 4);                                \
        (I).q0 = *(const float2*)(qf + rb);     (I).q1 = *(const float2*)(qf + rb + 2); \
        (I).q2 = *(const float2*)(qf + rb + 4);                                \
        (I).vt = kv[_t * (HH * 256) + h * 256 + 128 + v];                      \
        (I).bt = big[(long)_t * NBIG + 2880 + h];                              \
        (I).qk = qkb[_t * HH + h];                                             \
    } while (0)

    #define RSTEP(I, t) do {                                                   \
        s0 *= (I).e0.x; s1 *= (I).e0.y; s2 *= (I).e1.x;                        \
        s3 *= (I).e1.y; s4 *= (I).e2.x; s5 *= (I).e2.y;                        \
        float kse = fmaf(s0, (I).k0.x, fmaf(s1, (I).k0.y, fmaf(s2, (I).k1.x,   \
                    fmaf(s3, (I).k1.y, fmaf(s4, (I).k2.x, s5 * (I).k2.y)))));  \
        float qse = fmaf(s0, (I).q0.x, fmaf(s1, (I).q0.y, fmaf(s2, (I).q1.x,   \
                    fmaf(s3, (I).q1.y, fmaf(s4, (I).q2.x, s5 * (I).q2.y)))));  \
        _Pragma("unroll")                                                      \
        for (int off = 16; off; off >>= 1) {                                   \
            kse += __shfl_xor_sync(0xffffffffu, kse, off);                     \
            qse += __shfl_xor_sync(0xffffffffu, qse, off);                     \
        }                                                                      \
        const float u = (I).bt * ((I).vt - kse);                               \
        float ov = fmaf((I).qk, u, qse);                                       \
        s0 = fmaf((I).k0.x, u, s0); s1 = fmaf((I).k0.y, u, s1);                \
        s2 = fmaf((I).k1.x, u, s2); s3 = fmaf((I).k1.y, u, s3);                \
        s4 = fmaf((I).k2.x, u, s4); s5 = fmaf((I).k2.y, u, s5);                \
        if (lane == 0) {                                                       \
            if (ov != ov) ov = 0.f;                                            \
            ov = fminf(fmaxf(ov, -10000.f), 10000.f);                          \
            o[(t) * (HH * DV) + h * DV + v] = ov;                              \
        }                                                                      \
    } while (0)

    RecIn ia, ib, ic, id;
    RLOAD(ia, 0);
    RLOAD(ib, 1);
    RLOAD(ic, 2);
    for (int t = 0; t < TT; t += 4) {
        RLOAD(id, t + 3);
        RSTEP(ia, t);
        RLOAD(ia, t + 4);
        RSTEP(ib, t + 1);
        RLOAD(ib, t + 5);
        RSTEP(ic, t + 2);
        RLOAD(ic, t + 6);
        RSTEP(id, t + 3);
    }
    #undef RLOAD
    #undef RSTEP
}

// ---------------- launch ----------------
extern "C" void kernel_launch(void* const* d_in, const int* in_sizes, int n_in,
                              void* d_out, int out_size) {
    (void)in_sizes; (void)n_in; (void)out_size;
    const float* x         = (const float*)d_in[0];
    const float* wq_a      = (const float*)d_in[3];
    const float* q_norm_w  = (const float*)d_in[4];
    const float* wq_b      = (const float*)d_in[5];
    const float* wkv_a     = (const float*)d_in[6];
    const float* kv_norm_w = (const float*)d_in[7];
    const float* wkv_b     = (const float*)d_in[8];
    const float* wg_w      = (const float*)d_in[9];
    const float* wg_b      = (const float*)d_in[10];
    const float* wb        = (const float*)d_in[11];
    const float* wo        = (const float*)d_in[12];
    float* out = (float*)d_out;

    float *bc, *big, *qn, *kvn, *q, *kv, *kf, *qkb, *ov;
    cudaGetSymbolAddress((void**)&bc,  d_bc);
    cudaGetSymbolAddress((void**)&big, d_big);
    cudaGetSymbolAddress((void**)&qn,  d_qn);
    cudaGetSymbolAddress((void**)&kvn, d_kvn);
    cudaGetSymbolAddress((void**)&q,   d_q);
    cudaGetSymbolAddress((void**)&kv,  d_kv);
    cudaGetSymbolAddress((void**)&kf,  d_kf);
    cudaGetSymbolAddress((void**)&qkb, d_qk);
    cudaGetSymbolAddress((void**)&ov,  d_ov);

    concat_w<<<dim3(NBIG / 128, DIMX), 128>>>(wq_a, wkv_a, wg_w, wb, bc);

    // Stage 1: big = x @ [wq_a | wkv_a | wg_w | wb] (+ sigmoid epilogues)
    tgemm_kernel<1><<<dim3(NBIG / BN, TT / BM), 256>>>(NBIG, DIMX, x, DIMX, bc, NBIG, wg_b, big, NBIG);

    // Stage 2: fused RMS norms
    rms_fused<<<TT, 256>>>(big, q_norm_w, kv_norm_w, qn, kvn);

    // Stage 3: batched up-projections
    tgemm_dual_kernel<<<dim3(2048 / BN, TT / BM, 2), 256>>>(
        1536, QLR,  qn,  wq_b,  q,
        2048, KVLR, kvn, wkv_b, kv);

    // Stage 4: l2norm q/k, assemble k, precompute qk
    prep_kernel<<<TT * HH, 192>>>(q, kv, big, kf, qkb);

    // Stage 5: sequential KDA recurrence (dist-3 prefetch, 2 butterflies/step)
    kda_rec<<<128, 256>>>(q, kf, big, kv, qkb, ov);

    // Stage 6: output projection (plain TF32)
    tgemm_kernel<0><<<dim3(DIMX / BN, TT / BM), 256>>>(DIMX, DIMX, ov, DIMX, wo, DIMX, nullptr, out, DIMX);
}

// round 14
// speedup vs baseline: 1.3887x; 1.0401x over previous
#include <cuda_runtime.h>
#include <math.h>

// Problem constants
#define TT    1024
#define DIMX  1024
#define HH    8
#define DK    192
#define DV    128
#define QLR   768
#define KVLR  512
#define DROPE 64

#define NBIG 2944
#define CC   16            // chunk length
#define NCH  (TT / CC)     // 64 chunks

// ---------------- scratch ----------------
__device__ float d_bc  [DIMX * NBIG];
__device__ float d_big [TT * NBIG];
__device__ float d_qn  [TT * QLR];
__device__ float d_kvn [TT * KVLR];
__device__ float d_q   [TT * HH * DK];
__device__ float d_kv  [TT * HH * 256];
__device__ float d_kf  [TT * HH * DK];
__device__ float d_qk  [TT * HH];
__device__ float d_ov  [TT * HH * DV];
// chunked-recurrence scratch
__device__ float d_wch [NCH * HH * CC * DK];   // w = k .* a
__device__ float d_kch [NCH * HH * CC * DK];   // kappa = k ./ a
__device__ float d_qch [NCH * HH * CC * DK];   // qt = q .* a
__device__ float d_a16 [NCH * HH * DK];        // a at chunk end
__device__ float d_Nm  [NCH * HH * CC * CC];   // (I + B Mstrict)^-1 B
__device__ float d_Gm  [NCH * HH * CC * CC];   // tril(qt kappa^T)

// ================= TF32 tensor-core GEMM (double-buffered, cp.async B) =================
#define BM 64
#define BN 128
#define BK 16

__device__ __forceinline__ unsigned f2tf(float f) {
    unsigned u;
    asm("cvt.rna.tf32.f32 %0, %1;" : "=r"(u) : "f"(f));
    return u;
}

__device__ __forceinline__ void mma_tf32(float* c, const unsigned* a, const unsigned* b) {
    asm volatile(
        "mma.sync.aligned.m16n8k8.row.col.f32.tf32.tf32.f32 "
        "{%0,%1,%2,%3}, {%4,%5,%6,%7}, {%8,%9}, {%0,%1,%2,%3};\n"
        : "+f"(c[0]), "+f"(c[1]), "+f"(c[2]), "+f"(c[3])
        : "r"(a[0]), "r"(a[1]), "r"(a[2]), "r"(a[3]), "r"(b[0]), "r"(b[1]));
}

__device__ __forceinline__ void cp16(float* dst, const float* src) {
    unsigned s = (unsigned)__cvta_generic_to_shared(dst);
    asm volatile("cp.async.ca.shared.global [%0], [%1], 16;\n" :: "r"(s), "l"(src));
}
#define CP_COMMIT() asm volatile("cp.async.commit_group;\n" ::: "memory")
#define CP_WAIT0()  asm volatile("cp.async.wait_group 0;\n" ::: "memory")

__device__ __forceinline__ float epi1(float v, int gc, const float* __restrict__ bias) {
    if (gc >= 1344 && gc < 2888) {
        float b = (gc < 2880) ? bias[gc - 1344] : 0.f;
        v = 1.f / (1.f + expf(-(v + b)));
    }
    return v;
}

template <int EPI>
__device__ __forceinline__ void tgemm_core(int N, int K,
                                           const float* __restrict__ A, int lda,
                                           const float* __restrict__ B, int ldb,
                                           const float* __restrict__ bias,
                                           float* __restrict__ C, int ldc,
                                           float* sA, float* sB) {
    const int tid  = threadIdx.x;
    const int crow = blockIdx.y * BM;
    const int ccol = blockIdx.x * BN;

    const int wid  = tid >> 5;
    const int lane = tid & 31;
    const int lq   = lane >> 2;
    const int lr   = lane & 3;
    const int rm   = (wid & 1) * 32;
    const int cn   = (wid >> 1) * 32;

    const int am  = tid >> 2;
    const int ak4 = (tid & 3) * 4;
    const int bk  = tid >> 4;
    const int bc8 = (tid & 15) * 8;
    const int swb = (((bk & 3) ^ ((bk >> 2) & 3)) << 3);

    float acc[2][4][4] = {};
    float4 aR;

    aR = *reinterpret_cast<const float4*>(&A[(long)(crow + am) * lda + ak4]);
    cp16(&sB[bk * BN + ((bc8) ^ swb)],     &B[(long)bk * ldb + ccol + bc8]);
    cp16(&sB[bk * BN + ((bc8 + 4) ^ swb)], &B[(long)bk * ldb + ccol + bc8 + 4]);
    CP_COMMIT();
    {
        const float av[4] = {aR.x, aR.y, aR.z, aR.w};
        #pragma unroll
        for (int i = 0; i < 4; ++i) {
            const int k  = ak4 + i;
            const int sw = (((k & 3) ^ ((k >> 2) & 3)) << 3);
            sA[k * BM + (am ^ sw)] = av[i];
        }
    }
    if (K > BK)
        aR = *reinterpret_cast<const float4*>(&A[(long)(crow + am) * lda + BK + ak4]);
    CP_WAIT0();
    __syncthreads();

    int buf = 0;
    for (int k0 = 0; k0 < K; k0 += BK, buf ^= 1) {
        float* cA = sA + buf * (BK * BM);
        float* cB = sB + buf * (BK * BN);
        const int nxt = buf ^ 1;

        if (k0 + BK < K) {
            float* nB = sB + nxt * (BK * BN);
            cp16(&nB[bk * BN + ((bc8) ^ swb)],     &B[(long)(k0 + BK + bk) * ldb + ccol + bc8]);
            cp16(&nB[bk * BN + ((bc8 + 4) ^ swb)], &B[(long)(k0 + BK + bk) * ldb + ccol + bc8 + 4]);
            CP_COMMIT();
            float* nA = sA + nxt * (BK * BM);
            const float av[4] = {aR.x, aR.y, aR.z, aR.w};
            #pragma unroll
            for (int i = 0; i < 4; ++i) {
                const int k  = ak4 + i;
                const int sw = (((k & 3) ^ ((k >> 2) & 3)) << 3);
                nA[k * BM + (am ^ sw)] = av[i];
            }
            if (k0 + 2 * BK < K)
                aR = *reinterpret_cast<const float4*>(&A[(long)(crow + am) * lda + k0 + 2 * BK + ak4]);
        }

        #pragma unroll
        for (int k8 = 0; k8 < BK; k8 += 8) {
            const int f0 = ((lr ^ (k8 >> 2)) & 3) << 3;
            const int f1 = f0 ^ 8;
            unsigned af[2][4], bf[4][2];
            #pragma unroll
            for (int mt = 0; mt < 2; ++mt) {
                const int r = rm + mt * 16 + lq;
                af[mt][0] = f2tf(cA[(k8 + lr) * BM + (r ^ f0)]);
                af[mt][1] = f2tf(cA[(k8 + lr) * BM + ((r + 8) ^ f0)]);
                af[mt][2] = f2tf(cA[(k8 + lr + 4) * BM + (r ^ f1)]);
                af[mt][3] = f2tf(cA[(k8 + lr + 4) * BM + ((r + 8) ^ f1)]);
            }
            #pragma unroll
            for (int nt = 0; nt < 4; ++nt) {
                const int c = cn + nt * 8 + lq;
                bf[nt][0] = f2tf(cB[(k8 + lr) * BN + (c ^ f0)]);
                bf[nt][1] = f2tf(cB[(k8 + lr + 4) * BN + (c ^ f1)]);
            }
            #pragma unroll
            for (int mt = 0; mt < 2; ++mt)
                #pragma unroll
                for (int nt = 0; nt < 4; ++nt)
                    mma_tf32(acc[mt][nt], af[mt], bf[nt]);
        }
        CP_WAIT0();
        __syncthreads();
    }

    #pragma unroll
    for (int mt = 0; mt < 2; ++mt) {
        const int row = crow + rm + mt * 16 + lq;
        #pragma unroll
        for (int nt = 0; nt < 4; ++nt) {
            const int col = ccol + cn + nt * 8 + lr * 2;
            float v0 = acc[mt][nt][0], v1 = acc[mt][nt][1];
            float v2 = acc[mt][nt][2], v3 = acc[mt][nt][3];
            if (EPI == 1) {
                v0 = epi1(v0, col, bias);     v1 = epi1(v1, col + 1, bias);
                v2 = epi1(v2, col, bias);     v3 = epi1(v3, col + 1, bias);
            }
            *reinterpret_cast<float2*>(&C[(long)row * ldc + col])       = make_float2(v0, v1);
            *reinterpret_cast<float2*>(&C[(long)(row + 8) * ldc + col]) = make_float2(v2, v3);
        }
    }
}

template <int EPI>
__global__ __launch_bounds__(256, 2)
void tgemm_kernel(int N, int K, const float* __restrict__ A, int lda,
                  const float* __restrict__ B, int ldb,
                  const float* __restrict__ bias, float* __restrict__ C, int ldc) {
    __shared__ float sA[2 * BK * BM];
    __shared__ float sB[2 * BK * BN];
    tgemm_core<EPI>(N, K, A, lda, B, ldb, bias, C, ldc, sA, sB);
}

__global__ __launch_bounds__(256, 2)
void tgemm_dual_kernel(int N0, int K0, const float* __restrict__ A0,
                       const float* __restrict__ B0, float* __restrict__ C0,
                       int N1, int K1, const float* __restrict__ A1,
                       const float* __restrict__ B1, float* __restrict__ C1) {
    __shared__ float sA[2 * BK * BM];
    __shared__ float sB[2 * BK * BN];
    if (blockIdx.z == 0) {
        if ((int)blockIdx.x * BN >= N0) return;
        tgemm_core<0>(N0, K0, A0, K0, B0, N0, nullptr, C0, N0, sA, sB);
    } else {
        tgemm_core<0>(N1, K1, A1, K1, B1, N1, nullptr, C1, N1, sA, sB);
    }
}

// ---------------- stage-1 weight concat ----------------
__global__ void concat_w(const float* __restrict__ wq_a,
                         const float* __restrict__ wkv_a,
                         const float* __restrict__ wg_w,
                         const float* __restrict__ wb,
                         float* __restrict__ Bc) {
    const int c = blockIdx.x * 128 + threadIdx.x;
    const int r = blockIdx.y;
    float v;
    if      (c < 768)  v = wq_a [r * 768  + c];
    else if (c < 1344) v = wkv_a[r * 576  + (c - 768)];
    else if (c < 2880) v = wg_w [r * 1536 + (c - 1344)];
    else if (c < 2888) v = wb   [r * 8    + (c - 2880)];
    else               v = 0.f;
    Bc[(long)r * NBIG + c] = v;
}

// ---------------- fused row RMS norms ----------------
__device__ __forceinline__ void rms_row(const float* __restrict__ row,
                                        const float* __restrict__ w,
                                        float* __restrict__ out, int n) {
    float ss = 0.f;
    for (int i = threadIdx.x; i < n; i += 256) {
        float v = row[i];
        ss += v * v;
    }
    #pragma unroll
    for (int off = 16; off; off >>= 1)
        ss += __shfl_xor_sync(0xffffffffu, ss, off);
    __shared__ float red[8];
    __shared__ float scale_s;
    const int wid = threadIdx.x >> 5;
    if ((threadIdx.x & 31) == 0) red[wid] = ss;
    __syncthreads();
    if (threadIdx.x == 0) {
        float tot = 0.f;
        #pragma unroll
        for (int i = 0; i < 8; ++i) tot += red[i];
        scale_s = rsqrtf(tot / (float)n + 1e-5f);
    }
    __syncthreads();
    const float sc = scale_s;
    for (int i = threadIdx.x; i < n; i += 256)
        out[i] = row[i] * sc * w[i];
    __syncthreads();
}

__global__ void rms_fused(const float* __restrict__ big,
                          const float* __restrict__ qw,
                          const float* __restrict__ kvw,
                          float* __restrict__ qn,
                          float* __restrict__ kvn) {
    const int t = blockIdx.x;
    rms_row(big + (long)t * NBIG,       qw,  qn  + (long)t * QLR,  QLR);
    rms_row(big + (long)t * NBIG + 768, kvw, kvn + (long)t * KVLR, KVLR);
}

// ---------------- prep: l2norm q/k, assemble k ----------------
__global__ void prep_kernel(float* __restrict__ q,
                            const float* __restrict__ kv,
                            const float* __restrict__ big,
                            float* __restrict__ kf) {
    const int t = blockIdx.x >> 3;
    const int h = blockIdx.x & 7;
    const int i = threadIdx.x;  // 0..191

    const int qidx = t * (HH * DK) + h * DK + i;
    const float qv = q[qidx];
    const float kvv = (i < 128) ? kv[t * (HH * 256) + h * 256 + i]
                                : big[(long)t * NBIG + 1280 + (i - 128)];

    float q2 = qv * qv, k2 = kvv * kvv;
    #pragma unroll
    for (int off = 16; off; off >>= 1) {
        q2 += __shfl_xor_sync(0xffffffffu, q2, off);
        k2 += __shfl_xor_sync(0xffffffffu, k2, off);
    }
    __shared__ float sq[6], sk[6];
    __shared__ float scl[2];
    const int wid = threadIdx.x >> 5;
    if ((threadIdx.x & 31) == 0) { sq[wid] = q2; sk[wid] = k2; }
    __syncthreads();
    if (threadIdx.x == 0) {
        float a = 0.f, b = 0.f;
        #pragma unroll
        for (int j = 0; j < 6; ++j) { a += sq[j]; b += sk[j]; }
        scl[0] = rsqrtf(a + 1e-6f) * 0.07216878364870322f;
        scl[1] = rsqrtf(b + 1e-6f);
    }
    __syncthreads();
    q[qidx] = qv * scl[0];
    kf[qidx] = kvv * scl[1];
}

// ================= chunked KDA: prepass =================
// block = (chunk c, head h): computes a, w=k.*a, kappa=k./a, qt=q.*a,
// M = tril_strict(W kappa^T), G = tril(qt kappa^T), N = (I + B Mstrict)^-1 B.
__global__ __launch_bounds__(256)
void chunk_pre(const float* __restrict__ qf,
               const float* __restrict__ kf,
               const float* __restrict__ big,
               float* __restrict__ wg, float* __restrict__ kg,
               float* __restrict__ qg, float* __restrict__ a16g,
               float* __restrict__ Ng, float* __restrict__ Gg) {
    const int ch = blockIdx.x;      // c*8 + h
    const int c  = ch >> 3, h = ch & 7;
    __shared__ float ws[CC][193], ks[CC][193], qs[CC][193];
    __shared__ float ms[CC * CC];
    __shared__ float bs[CC];
    const int tid = threadIdx.x;

    if (tid < 192) {
        const int d = tid;
        float a = 1.f;
        for (int t = 0; t < CC; ++t) {
            const long row = (long)(c * CC + t);
            const float e  = big[row * NBIG + 1344 + h * 192 + d];
            a *= e;
            const float kd = kf[row * 1536 + h * 192 + d];
            const float qd = qf[row * 1536 + h * 192 + d];
            const float w  = kd * a;
            const float ka = kd / a;
            const float qa = qd * a;
            ws[t][d] = w; ks[t][d] = ka; qs[t][d] = qa;
            const long g = ((long)ch * CC + t) * 192 + d;
            wg[g] = w; kg[g] = ka; qg[g] = qa;
        }
        a16g[(long)ch * 192 + d] = a;
    }
    if (tid < CC)
        bs[tid] = big[(long)(c * CC + tid) * NBIG + 2880 + h];
    __syncthreads();

    // M (strict lower) and G (lower incl diag)
    {
        const int t = tid >> 4, s = tid & 15;
        float m = 0.f, g = 0.f;
        float m1 = 0.f, g1 = 0.f;   // dual accumulators
        for (int d = 0; d < 192; d += 2) {
            float kd0 = ks[s][d], kd1 = ks[s][d + 1];
            m  = fmaf(ws[t][d],     kd0, m);
            m1 = fmaf(ws[t][d + 1], kd1, m1);
            g  = fmaf(qs[t][d],     kd0, g);
            g1 = fmaf(qs[t][d + 1], kd1, g1);
        }
        m += m1; g += g1;
        ms[tid] = (s < t) ? m : 0.f;
        Gg[(long)ch * 256 + tid] = (s <= t) ? g : 0.f;
    }
    __syncthreads();

    // N solve: N[t][j] = beta_t * (delta(t==j) - sum_{s<t} M[t][s] N[s][j]); one warp, lane j
    if (tid < 16) {
        const int j = tid;
        float n[CC];
        #pragma unroll
        for (int t = 0; t < CC; ++t) {
            float acc = (t == j) ? 1.f : 0.f;
            #pragma unroll
            for (int s = 0; s < CC; ++s)
                if (s < t) acc = fmaf(-ms[t * 16 + s], n[s], acc);
            n[t] = bs[t] * acc;
        }
        #pragma unroll
        for (int t = 0; t < CC; ++t)
            Ng[(long)ch * 256 + t * 16 + j] = n[t];
    }
}

// ================= chunked KDA: sequential kernel =================
// block = (head h, v-tile of 16). S[192][16] lives in (dynamic) smem across 64 chunks.
#define SEQ_S    0                         // S: 192*17
#define SEQ_W    (192 * 17)                // w: 16*192
#define SEQ_K    (SEQ_W + CC * 192)        // kappa
#define SEQ_Q    (SEQ_K + CC * 192)        // qt
#define SEQ_N    (SEQ_Q + CC * 192)        // N: 256
#define SEQ_G    (SEQ_N + 256)
#define SEQ_XV   (SEQ_G + 256)             // V then X
#define SEQ_U    (SEQ_XV + 256)
#define SEQ_A16  (SEQ_U + 256)             // 192
#define SEQ_SIZE ((SEQ_A16 + 192) * 4)     // bytes

__global__ __launch_bounds__(256)
void chunk_seq(const float* __restrict__ wg, const float* __restrict__ kg,
               const float* __restrict__ qg, const float* __restrict__ a16g,
               const float* __restrict__ Ng, const float* __restrict__ Gg,
               const float* __restrict__ kvb, float* __restrict__ o) {
    extern __shared__ float dyn[];
    float* Ss  = dyn + SEQ_S;     // [d][j] stride 17
    float* ws  = dyn + SEQ_W;     // [t][d] stride 192
    float* ksm = dyn + SEQ_K;
    float* qsm = dyn + SEQ_Q;
    float* Ns  = dyn + SEQ_N;
    float* Gs  = dyn + SEQ_G;
    float* XVs = dyn + SEQ_XV;
    float* Us  = dyn + SEQ_U;
    float* a16 = dyn + SEQ_A16;

    const int h     = blockIdx.x >> 3;
    const int vbase = (blockIdx.x & 7) * 16;
    const int tid   = threadIdx.x;
    const int t     = tid >> 4;       // 0..15
    const int j     = tid & 15;       // 0..15

    for (int i = tid; i < 192 * 17; i += 256) Ss[i] = 0.f;
    __syncthreads();

    for (int c = 0; c < NCH; ++c) {
        const int ch = c * 8 + h;
        // load chunk data
        for (int i = tid; i < CC * 192; i += 256) {
            const long g = (long)ch * (CC * 192) + i;
            ws[i]  = wg[g];
            ksm[i] = kg[g];
            qsm[i] = qg[g];
        }
        Ns[tid] = Ng[(long)ch * 256 + tid];
        Gs[tid] = Gg[(long)ch * 256 + tid];
        if (tid < 192) a16[tid] = a16g[(long)ch * 192 + tid];
        XVs[tid] = kvb[(long)(c * CC + t) * 2048 + h * 256 + 128 + vbase + j];
        __syncthreads();

        // Y0[t][j] = sum_d w[t][d] S[d][j]; Opart = sum_d qt[t][d] S[d][j]
        float y0 = 0.f, y1 = 0.f, o0 = 0.f, o1 = 0.f;
        const float* wrow = ws  + t * 192;
        const float* qrow = qsm + t * 192;
        for (int d = 0; d < 192; d += 2) {
            const float s0 = Ss[d * 17 + j];
            const float s1 = Ss[(d + 1) * 17 + j];
            y0 = fmaf(wrow[d],     s0, y0);
            y1 = fmaf(wrow[d + 1], s1, y1);
            o0 = fmaf(qrow[d],     s0, o0);
            o1 = fmaf(qrow[d + 1], s1, o1);
        }
        float ov = o0 + o1;
        XVs[tid] = XVs[tid] - (y0 + y1);
        __syncthreads();

        // U = N X
        float u = 0.f;
        #pragma unroll
        for (int s = 0; s < CC; ++s)
            u = fmaf(Ns[t * 16 + s], XVs[s * 16 + j], u);
        Us[tid] = u;
        __syncthreads();

        // O += G U; write
        #pragma unroll
        for (int s = 0; s < CC; ++s)
            ov = fmaf(Gs[t * 16 + s], Us[s * 16 + j], ov);
        if (ov != ov) ov = 0.f;
        ov = fminf(fmaxf(ov, -10000.f), 10000.f);
        o[(long)(c * CC + t) * 1024 + h * 128 + vbase + j] = ov;

        // S[d][j] = a16[d] * (S[d][j] + sum_s kappa[s][d] U[s][j])
        float ureg[CC];
        #pragma unroll
        for (int s = 0; s < CC; ++s) ureg[s] = Us[s * 16 + j];
        #pragma unroll
        for (int rep = 0; rep < 12; ++rep) {
            const int d = rep * 16 + t;
            float acc = Ss[d * 17 + j];
            #pragma unroll
            for (int s = 0; s < CC; ++s)
                acc = fmaf(ksm[s * 192 + d], ureg[s], acc);
            Ss[d * 17 + j] = a16[d] * acc;
        }
        __syncthreads();
    }
}

// ---------------- launch ----------------
extern "C" void kernel_launch(void* const* d_in, const int* in_sizes, int n_in,
                              void* d_out, int out_size) {
    (void)in_sizes; (void)n_in; (void)out_size;
    const float* x         = (const float*)d_in[0];
    const float* wq_a      = (const float*)d_in[3];
    const float* q_norm_w  = (const float*)d_in[4];
    const float* wq_b      = (const float*)d_in[5];
    const float* wkv_a     = (const float*)d_in[6];
    const float* kv_norm_w = (const float*)d_in[7];
    const float* wkv_b     = (const float*)d_in[8];
    const float* wg_w      = (const float*)d_in[9];
    const float* wg_b      = (const float*)d_in[10];
    const float* wb        = (const float*)d_in[11];
    const float* wo        = (const float*)d_in[12];
    float* out = (float*)d_out;

    float *bc, *big, *qn, *kvn, *q, *kv, *kf, *ov;
    float *wch, *kch, *qch, *a16, *Nm, *Gm;
    cudaGetSymbolAddress((void**)&bc,  d_bc);
    cudaGetSymbolAddress((void**)&big, d_big);
    cudaGetSymbolAddress((void**)&qn,  d_qn);
    cudaGetSymbolAddress((void**)&kvn, d_kvn);
    cudaGetSymbolAddress((void**)&q,   d_q);
    cudaGetSymbolAddress((void**)&kv,  d_kv);
    cudaGetSymbolAddress((void**)&kf,  d_kf);
    cudaGetSymbolAddress((void**)&ov,  d_ov);
    cudaGetSymbolAddress((void**)&wch, d_wch);
    cudaGetSymbolAddress((void**)&kch, d_kch);
    cudaGetSymbolAddress((void**)&qch, d_qch);
    cudaGetSymbolAddress((void**)&a16, d_a16);
    cudaGetSymbolAddress((void**)&Nm,  d_Nm);
    cudaGetSymbolAddress((void**)&Gm,  d_Gm);

    static int smem_set = 0;
    if (!smem_set) {
        cudaFuncSetAttribute(chunk_seq, cudaFuncAttributeMaxDynamicSharedMemorySize, SEQ_SIZE);
        smem_set = 1;
    }

    concat_w<<<dim3(NBIG / 128, DIMX), 128>>>(wq_a, wkv_a, wg_w, wb, bc);

    // Stage 1: big = x @ [wq_a | wkv_a | wg_w | wb] (+ sigmoid epilogues)
    tgemm_kernel<1><<<dim3(NBIG / BN, TT / BM), 256>>>(NBIG, DIMX, x, DIMX, bc, NBIG, wg_b, big, NBIG);

    // Stage 2: fused RMS norms
    rms_fused<<<TT, 256>>>(big, q_norm_w, kv_norm_w, qn, kvn);

    // Stage 3: batched up-projections
    tgemm_dual_kernel<<<dim3(2048 / BN, TT / BM, 2), 256>>>(
        1536, QLR,  qn,  wq_b,  q,
        2048, KVLR, kvn, wkv_b, kv);

    // Stage 4: l2norm q/k, assemble k
    prep_kernel<<<TT * HH, 192>>>(q, kv, big, kf);

    // Stage 5a: chunk prepass (fully parallel over 64 chunks x 8 heads)
    chunk_pre<<<NCH * HH, 256>>>(q, kf, big, wch, kch, qch, a16, Nm, Gm);

    // Stage 5b: sequential chunk scan (64 blocks = 8 heads x 8 v-tiles)
    chunk_seq<<<HH * 8, 256, SEQ_SIZE>>>(wch, kch, qch, a16, Nm, Gm, kv, ov);

    // Stage 6: output projection (plain TF32)
    tgemm_kernel<0><<<dim3(DIMX / BN, TT / BM), 256>>>(DIMX, DIMX, ov, DIMX, wo, DIMX, nullptr, out, DIMX);
}

// round 15
// speedup vs baseline: 1.7463x; 1.2575x over previous
#include <cuda_runtime.h>
#include <math.h>

// Problem constants
#define TT    1024
#define DIMX  1024
#define HH    8
#define DK    192
#define DV    128
#define QLR   768
#define KVLR  512
#define DROPE 64

#define NBIG 2944
#define CC   16            // chunk length
#define NCH  (TT / CC)     // 64 chunks

// ---------------- scratch ----------------
__device__ float d_bc  [DIMX * NBIG];
__device__ float d_big [TT * NBIG];
__device__ float d_qn  [TT * QLR];
__device__ float d_kvn [TT * KVLR];
__device__ float d_q   [TT * HH * DK];
__device__ float d_kv  [TT * HH * 256];
__device__ float d_kf  [TT * HH * DK];
__device__ float d_ov  [TT * HH * DV];
// chunked-recurrence scratch
__device__ float d_wch [NCH * HH * CC * DK];   // w = k .* a
__device__ float d_kch [NCH * HH * CC * DK];   // kappa = k ./ a
__device__ float d_qch [NCH * HH * CC * DK];   // qt = q .* a
__device__ float d_a16 [NCH * HH * DK];        // a at chunk end
__device__ float d_Nm  [NCH * HH * CC * CC];   // (I + B Mstrict)^-1 B
__device__ float d_Gm  [NCH * HH * CC * CC];   // tril(qt kappa^T)

// ================= TF32 tensor-core GEMM (double-buffered, cp.async B) =================
#define BM 64
#define BN 128
#define BK 16

__device__ __forceinline__ unsigned f2tf(float f) {
    unsigned u;
    asm("cvt.rna.tf32.f32 %0, %1;" : "=r"(u) : "f"(f));
    return u;
}

__device__ __forceinline__ void mma_tf32(float* c, const unsigned* a, const unsigned* b) {
    asm volatile(
        "mma.sync.aligned.m16n8k8.row.col.f32.tf32.tf32.f32 "
        "{%0,%1,%2,%3}, {%4,%5,%6,%7}, {%8,%9}, {%0,%1,%2,%3};\n"
        : "+f"(c[0]), "+f"(c[1]), "+f"(c[2]), "+f"(c[3])
        : "r"(a[0]), "r"(a[1]), "r"(a[2]), "r"(a[3]), "r"(b[0]), "r"(b[1]));
}

__device__ __forceinline__ void cp16(float* dst, const float* src) {
    unsigned s = (unsigned)__cvta_generic_to_shared(dst);
    asm volatile("cp.async.ca.shared.global [%0], [%1], 16;\n" :: "r"(s), "l"(src));
}
#define CP_COMMIT() asm volatile("cp.async.commit_group;\n" ::: "memory")
#define CP_WAIT0()  asm volatile("cp.async.wait_group 0;\n" ::: "memory")

__device__ __forceinline__ float epi1(float v, int gc, const float* __restrict__ bias) {
    if (gc >= 1344 && gc < 2888) {
        float b = (gc < 2880) ? bias[gc - 1344] : 0.f;
        v = 1.f / (1.f + expf(-(v + b)));
    }
    return v;
}

template <int EPI>
__device__ __forceinline__ void tgemm_core(int N, int K,
                                           const float* __restrict__ A, int lda,
                                           const float* __restrict__ B, int ldb,
                                           const float* __restrict__ bias,
                                           float* __restrict__ C, int ldc,
                                           float* sA, float* sB) {
    const int tid  = threadIdx.x;
    const int crow = blockIdx.y * BM;
    const int ccol = blockIdx.x * BN;

    const int wid  = tid >> 5;
    const int lane = tid & 31;
    const int lq   = lane >> 2;
    const int lr   = lane & 3;
    const int rm   = (wid & 1) * 32;
    const int cn   = (wid >> 1) * 32;

    const int am  = tid >> 2;
    const int ak4 = (tid & 3) * 4;
    const int bk  = tid >> 4;
    const int bc8 = (tid & 15) * 8;
    const int swb = (((bk & 3) ^ ((bk >> 2) & 3)) << 3);

    float acc[2][4][4] = {};
    float4 aR;

    aR = *reinterpret_cast<const float4*>(&A[(long)(crow + am) * lda + ak4]);
    cp16(&sB[bk * BN + ((bc8) ^ swb)],     &B[(long)bk * ldb + ccol + bc8]);
    cp16(&sB[bk * BN + ((bc8 + 4) ^ swb)], &B[(long)bk * ldb + ccol + bc8 + 4]);
    CP_COMMIT();
    {
        const float av[4] = {aR.x, aR.y, aR.z, aR.w};
        #pragma unroll
        for (int i = 0; i < 4; ++i) {
            const int k  = ak4 + i;
            const int sw = (((k & 3) ^ ((k >> 2) & 3)) << 3);
            sA[k * BM + (am ^ sw)] = av[i];
        }
    }
    if (K > BK)
        aR = *reinterpret_cast<const float4*>(&A[(long)(crow + am) * lda + BK + ak4]);
    CP_WAIT0();
    __syncthreads();

    int buf = 0;
    for (int k0 = 0; k0 < K; k0 += BK, buf ^= 1) {
        float* cA = sA + buf * (BK * BM);
        float* cB = sB + buf * (BK * BN);
        const int nxt = buf ^ 1;

        if (k0 + BK < K) {
            float* nB = sB + nxt * (BK * BN);
            cp16(&nB[bk * BN + ((bc8) ^ swb)],     &B[(long)(k0 + BK + bk) * ldb + ccol + bc8]);
            cp16(&nB[bk * BN + ((bc8 + 4) ^ swb)], &B[(long)(k0 + BK + bk) * ldb + ccol + bc8 + 4]);
            CP_COMMIT();
            float* nA = sA + nxt * (BK * BM);
            const float av[4] = {aR.x, aR.y, aR.z, aR.w};
            #pragma unroll
            for (int i = 0; i < 4; ++i) {
                const int k  = ak4 + i;
                const int sw = (((k & 3) ^ ((k >> 2) & 3)) << 3);
                nA[k * BM + (am ^ sw)] = av[i];
            }
            if (k0 + 2 * BK < K)
                aR = *reinterpret_cast<const float4*>(&A[(long)(crow + am) * lda + k0 + 2 * BK + ak4]);
        }

        #pragma unroll
        for (int k8 = 0; k8 < BK; k8 += 8) {
            const int f0 = ((lr ^ (k8 >> 2)) & 3) << 3;
            const int f1 = f0 ^ 8;
            unsigned af[2][4], bf[4][2];
            #pragma unroll
            for (int mt = 0; mt < 2; ++mt) {
                const int r = rm + mt * 16 + lq;
                af[mt][0] = f2tf(cA[(k8 + lr) * BM + (r ^ f0)]);
                af[mt][1] = f2tf(cA[(k8 + lr) * BM + ((r + 8) ^ f0)]);
                af[mt][2] = f2tf(cA[(k8 + lr + 4) * BM + (r ^ f1)]);
                af[mt][3] = f2tf(cA[(k8 + lr + 4) * BM + ((r + 8) ^ f1)]);
            }
            #pragma unroll
            for (int nt = 0; nt < 4; ++nt) {
                const int c = cn + nt * 8 + lq;
                bf[nt][0] = f2tf(cB[(k8 + lr) * BN + (c ^ f0)]);
                bf[nt][1] = f2tf(cB[(k8 + lr + 4) * BN + (c ^ f1)]);
            }
            #pragma unroll
            for (int mt = 0; mt < 2; ++mt)
                #pragma unroll
                for (int nt = 0; nt < 4; ++nt)
                    mma_tf32(acc[mt][nt], af[mt], bf[nt]);
        }
        CP_WAIT0();
        __syncthreads();
    }

    #pragma unroll
    for (int mt = 0; mt < 2; ++mt) {
        const int row = crow + rm + mt * 16 + lq;
        #pragma unroll
        for (int nt = 0; nt < 4; ++nt) {
            const int col = ccol + cn + nt * 8 + lr * 2;
            float v0 = acc[mt][nt][0], v1 = acc[mt][nt][1];
            float v2 = acc[mt][nt][2], v3 = acc[mt][nt][3];
            if (EPI == 1) {
                v0 = epi1(v0, col, bias);     v1 = epi1(v1, col + 1, bias);
                v2 = epi1(v2, col, bias);     v3 = epi1(v3, col + 1, bias);
            }
            *reinterpret_cast<float2*>(&C[(long)row * ldc + col])       = make_float2(v0, v1);
            *reinterpret_cast<float2*>(&C[(long)(row + 8) * ldc + col]) = make_float2(v2, v3);
        }
    }
}

template <int EPI>
__global__ __launch_bounds__(256, 2)
void tgemm_kernel(int N, int K, const float* __restrict__ A, int lda,
                  const float* __restrict__ B, int ldb,
                  const float* __restrict__ bias, float* __restrict__ C, int ldc) {
    __shared__ float sA[2 * BK * BM];
    __shared__ float sB[2 * BK * BN];
    tgemm_core<EPI>(N, K, A, lda, B, ldb, bias, C, ldc, sA, sB);
}

__global__ __launch_bounds__(256, 2)
void tgemm_dual_kernel(int N0, int K0, const float* __restrict__ A0,
                       const float* __restrict__ B0, float* __restrict__ C0,
                       int N1, int K1, const float* __restrict__ A1,
                       const float* __restrict__ B1, float* __restrict__ C1) {
    __shared__ float sA[2 * BK * BM];
    __shared__ float sB[2 * BK * BN];
    if (blockIdx.z == 0) {
        if ((int)blockIdx.x * BN >= N0) return;
        tgemm_core<0>(N0, K0, A0, K0, B0, N0, nullptr, C0, N0, sA, sB);
    } else {
        tgemm_core<0>(N1, K1, A1, K1, B1, N1, nullptr, C1, N1, sA, sB);
    }
}

// ---------------- stage-1 weight concat ----------------
__global__ void concat_w(const float* __restrict__ wq_a,
                         const float* __restrict__ wkv_a,
                         const float* __restrict__ wg_w,
                         const float* __restrict__ wb,
                         float* __restrict__ Bc) {
    const int c = blockIdx.x * 128 + threadIdx.x;
    const int r = blockIdx.y;
    float v;
    if      (c < 768)  v = wq_a [r * 768  + c];
    else if (c < 1344) v = wkv_a[r * 576  + (c - 768)];
    else if (c < 2880) v = wg_w [r * 1536 + (c - 1344)];
    else if (c < 2888) v = wb   [r * 8    + (c - 2880)];
    else               v = 0.f;
    Bc[(long)r * NBIG + c] = v;
}

// ---------------- fused row RMS norms ----------------
__device__ __forceinline__ void rms_row(const float* __restrict__ row,
                                        const float* __restrict__ w,
                                        float* __restrict__ out, int n) {
    float ss = 0.f;
    for (int i = threadIdx.x; i < n; i += 256) {
        float v = row[i];
        ss += v * v;
    }
    #pragma unroll
    for (int off = 16; off; off >>= 1)
        ss += __shfl_xor_sync(0xffffffffu, ss, off);
    __shared__ float red[8];
    __shared__ float scale_s;
    const int wid = threadIdx.x >> 5;
    if ((threadIdx.x & 31) == 0) red[wid] = ss;
    __syncthreads();
    if (threadIdx.x == 0) {
        float tot = 0.f;
        #pragma unroll
        for (int i = 0; i < 8; ++i) tot += red[i];
        scale_s = rsqrtf(tot / (float)n + 1e-5f);
    }
    __syncthreads();
    const float sc = scale_s;
    for (int i = threadIdx.x; i < n; i += 256)
        out[i] = row[i] * sc * w[i];
    __syncthreads();
}

__global__ void rms_fused(const float* __restrict__ big,
                          const float* __restrict__ qw,
                          const float* __restrict__ kvw,
                          float* __restrict__ qn,
                          float* __restrict__ kvn) {
    const int t = blockIdx.x;
    rms_row(big + (long)t * NBIG,       qw,  qn  + (long)t * QLR,  QLR);
    rms_row(big + (long)t * NBIG + 768, kvw, kvn + (long)t * KVLR, KVLR);
}

// ---------------- prep: l2norm q/k, assemble k ----------------
__global__ void prep_kernel(float* __restrict__ q,
                            const float* __restrict__ kv,
                            const float* __restrict__ big,
                            float* __restrict__ kf) {
    const int t = blockIdx.x >> 3;
    const int h = blockIdx.x & 7;
    const int i = threadIdx.x;  // 0..191

    const int qidx = t * (HH * DK) + h * DK + i;
    const float qv = q[qidx];
    const float kvv = (i < 128) ? kv[t * (HH * 256) + h * 256 + i]
                                : big[(long)t * NBIG + 1280 + (i - 128)];

    float q2 = qv * qv, k2 = kvv * kvv;
    #pragma unroll
    for (int off = 16; off; off >>= 1) {
        q2 += __shfl_xor_sync(0xffffffffu, q2, off);
        k2 += __shfl_xor_sync(0xffffffffu, k2, off);
    }
    __shared__ float sq[6], sk[6];
    __shared__ float scl[2];
    const int wid = threadIdx.x >> 5;
    if ((threadIdx.x & 31) == 0) { sq[wid] = q2; sk[wid] = k2; }
    __syncthreads();
    if (threadIdx.x == 0) {
        float a = 0.f, b = 0.f;
        #pragma unroll
        for (int j = 0; j < 6; ++j) { a += sq[j]; b += sk[j]; }
        scl[0] = rsqrtf(a + 1e-6f) * 0.07216878364870322f;
        scl[1] = rsqrtf(b + 1e-6f);
    }
    __syncthreads();
    q[qidx] = qv * scl[0];
    kf[qidx] = kvv * scl[1];
}

// ================= chunked KDA: prepass =================
__global__ __launch_bounds__(256)
void chunk_pre(const float* __restrict__ qf,
               const float* __restrict__ kf,
               const float* __restrict__ big,
               float* __restrict__ wg, float* __restrict__ kg,
               float* __restrict__ qg, float* __restrict__ a16g,
               float* __restrict__ Ng, float* __restrict__ Gg) {
    const int ch = blockIdx.x;      // c*8 + h
    const int c  = ch >> 3, h = ch & 7;
    __shared__ float ws[CC][193], ks[CC][193], qs[CC][193];
    __shared__ float ms[CC * CC];
    __shared__ float bs[CC];
    const int tid = threadIdx.x;

    if (tid < 192) {
        const int d = tid;
        float a = 1.f;
        for (int t = 0; t < CC; ++t) {
            const long row = (long)(c * CC + t);
            const float e  = big[row * NBIG + 1344 + h * 192 + d];
            a *= e;
            const float kd = kf[row * 1536 + h * 192 + d];
            const float qd = qf[row * 1536 + h * 192 + d];
            const float w  = kd * a;
            const float ka = kd / a;
            const float qa = qd * a;
            ws[t][d] = w; ks[t][d] = ka; qs[t][d] = qa;
            const long g = ((long)ch * CC + t) * 192 + d;
            wg[g] = w; kg[g] = ka; qg[g] = qa;
        }
        a16g[(long)ch * 192 + d] = a;
    }
    if (tid < CC)
        bs[tid] = big[(long)(c * CC + tid) * NBIG + 2880 + h];
    __syncthreads();

    {
        const int t = tid >> 4, s = tid & 15;
        float m = 0.f, g = 0.f;
        float m1 = 0.f, g1 = 0.f;
        for (int d = 0; d < 192; d += 2) {
            float kd0 = ks[s][d], kd1 = ks[s][d + 1];
            m  = fmaf(ws[t][d],     kd0, m);
            m1 = fmaf(ws[t][d + 1], kd1, m1);
            g  = fmaf(qs[t][d],     kd0, g);
            g1 = fmaf(qs[t][d + 1], kd1, g1);
        }
        m += m1; g += g1;
        ms[tid] = (s < t) ? m : 0.f;
        Gg[(long)ch * 256 + tid] = (s <= t) ? g : 0.f;
    }
    __syncthreads();

    if (tid < 16) {
        const int j = tid;
        float n[CC];
        #pragma unroll
        for (int t = 0; t < CC; ++t) {
            float acc = (t == j) ? 1.f : 0.f;
            #pragma unroll
            for (int s = 0; s < CC; ++s)
                if (s < t) acc = fmaf(-ms[t * 16 + s], n[s], acc);
            n[t] = bs[t] * acc;
        }
        #pragma unroll
        for (int t = 0; t < CC; ++t)
            Ng[(long)ch * 256 + t * 16 + j] = n[t];
    }
}

// ================= chunked KDA: sequential kernel (v2) =================
// S stored [j][194] (row per v-column j, stride 194 -> conflict-free float2).
// All per-chunk inputs double-buffered via cp.async.
#define CS_SS   0                      // 16*194 = 3104
#define CS_W    3104                   // 2*3072
#define CS_K    (CS_W + 6144)
#define CS_Q    (CS_K + 6144)
#define CS_N    (CS_Q + 6144)          // 2*256
#define CS_G    (CS_N + 512)
#define CS_V    (CS_G + 512)
#define CS_A    (CS_V + 512)           // 2*192
#define CS_X    (CS_A + 384)
#define CS_U    (CS_X + 256)
#define CS_TOTF (CS_U + 256)
#define CS_BYTES (CS_TOTF * 4)

__global__ __launch_bounds__(256)
void chunk_seq(const float* __restrict__ wg, const float* __restrict__ kg,
               const float* __restrict__ qg, const float* __restrict__ a16g,
               const float* __restrict__ Ng, const float* __restrict__ Gg,
               const float* __restrict__ kvb, float* __restrict__ o) {
    extern __shared__ float dyn[];
    const int h     = blockIdx.x >> 3;
    const int vbase = (blockIdx.x & 7) * 16;
    const int tid   = threadIdx.x;
    const int t     = tid >> 4;       // 0..15
    const int j     = tid & 15;       // 0..15

    float* Ss = dyn + CS_SS;
    float* Xs = dyn + CS_X;
    float* Us = dyn + CS_U;

    for (int i = tid; i < 16 * 194; i += 256) Ss[i] = 0.f;

    #define CS_ISSUE(cc, b) do {                                                      \
        const int _ch = (cc) * 8 + h;                                                 \
        float* wB2 = dyn + CS_W + (b) * 3072;                                         \
        float* kB2 = dyn + CS_K + (b) * 3072;                                         \
        float* qB2 = dyn + CS_Q + (b) * 3072;                                         \
        const long gb = (long)_ch * 3072;                                             \
        for (int i = tid * 4; i < 3072; i += 1024) {                                  \
            cp16(wB2 + i, wg + gb + i);                                               \
            cp16(kB2 + i, kg + gb + i);                                               \
            cp16(qB2 + i, qg + gb + i);                                               \
        }                                                                             \
        if (tid < 64)        cp16(dyn + CS_N + (b) * 256 + tid * 4,                   \
                                  Ng + (long)_ch * 256 + tid * 4);                    \
        else if (tid < 128) { int u2 = tid - 64;                                      \
                              cp16(dyn + CS_G + (b) * 256 + u2 * 4,                   \
                                   Gg + (long)_ch * 256 + u2 * 4); }                  \
        else if (tid < 176) { int u2 = tid - 128;                                     \
                              cp16(dyn + CS_A + (b) * 192 + u2 * 4,                   \
                                   a16g + (long)_ch * 192 + u2 * 4); }                \
        else if (tid < 240) { int u2 = tid - 176; int tt = u2 >> 2, pp = u2 & 3;      \
                              cp16(dyn + CS_V + (b) * 256 + tt * 16 + pp * 4,         \
                                   kvb + (long)((cc) * 16 + tt) * 2048 + h * 256 + 128\
                                   + vbase + pp * 4); }                               \
        CP_COMMIT();                                                                  \
    } while (0)

    CS_ISSUE(0, 0);
    CP_WAIT0();
    __syncthreads();

    for (int c = 0; c < NCH; ++c) {
        const int cur = c & 1;
        if (c + 1 < NCH) CS_ISSUE(c + 1, cur ^ 1);

        const float* wB = dyn + CS_W + cur * 3072;
        const float* kB = dyn + CS_K + cur * 3072;
        const float* qB = dyn + CS_Q + cur * 3072;
        const float* NB = dyn + CS_N + cur * 256;
        const float* GB = dyn + CS_G + cur * 256;
        const float* VB = dyn + CS_V + cur * 256;
        const float* AB = dyn + CS_A + cur * 192;

        // ---- Y0 = W@S, Opart = Qt@S (thread (t,j)) ----
        const float* wrow = wB + t * 192;
        const float* qrow = qB + t * 192;
        const float* srow = Ss + j * 194;
        float y0 = 0.f, y1 = 0.f, y2 = 0.f, y3 = 0.f;
        float p0 = 0.f, p1 = 0.f, p2 = 0.f, p3 = 0.f;
        #pragma unroll
        for (int d = 0; d < 192; d += 4) {
            float4 w4 = *(const float4*)(wrow + d);
            float4 q4 = *(const float4*)(qrow + d);
            float2 sa = *(const float2*)(srow + d);
            float2 sb = *(const float2*)(srow + d + 2);
            y0 = fmaf(w4.x, sa.x, y0); y1 = fmaf(w4.y, sa.y, y1);
            y2 = fmaf(w4.z, sb.x, y2); y3 = fmaf(w4.w, sb.y, y3);
            p0 = fmaf(q4.x, sa.x, p0); p1 = fmaf(q4.y, sa.y, p1);
            p2 = fmaf(q4.z, sb.x, p2); p3 = fmaf(q4.w, sb.y, p3);
        }
        float ov = (p0 + p1) + (p2 + p3);
        Xs[t * 16 + j] = VB[t * 16 + j] - ((y0 + y1) + (y2 + y3));
        __syncthreads();

        // ---- U = N X ----
        float u = 0.f;
        #pragma unroll
        for (int s = 0; s < CC; ++s)
            u = fmaf(NB[t * 16 + s], Xs[s * 16 + j], u);
        Us[t * 16 + j] = u;
        __syncthreads();

        // ---- O += G U; write ----
        #pragma unroll
        for (int s = 0; s < CC; ++s)
            ov = fmaf(GB[t * 16 + s], Us[s * 16 + j], ov);
        if (ov != ov) ov = 0.f;
        ov = fminf(fmaxf(ov, -10000.f), 10000.f);
        o[(long)(c * CC + t) * 1024 + h * 128 + vbase + j] = ov;

        // ---- S[j][d] = a(d)*(S[j][d] + sum_s kappa[s][d] U[s][j]), d = t*12..+11 ----
        {
            float ur[CC];
            #pragma unroll
            for (int s = 0; s < CC; ++s) ur[s] = Us[s * 16 + j];
            float* sr = Ss + j * 194 + t * 12;
            float sreg[12];
            #pragma unroll
            for (int i2 = 0; i2 < 12; i2 += 2) {
                float2 tmp = *(const float2*)(sr + i2);
                sreg[i2] = tmp.x; sreg[i2 + 1] = tmp.y;
            }
            const float* kp = kB + t * 12;
            #pragma unroll
            for (int s = 0; s < CC; ++s) {
                const float* krow = kp + s * 192;
                float4 k0 = *(const float4*)(krow);
                float4 k1 = *(const float4*)(krow + 4);
                float4 k2 = *(const float4*)(krow + 8);
                const float us = ur[s];
                sreg[0] = fmaf(k0.x, us, sreg[0]);  sreg[1] = fmaf(k0.y, us, sreg[1]);
                sreg[2] = fmaf(k0.z, us, sreg[2]);  sreg[3] = fmaf(k0.w, us, sreg[3]);
                sreg[4] = fmaf(k1.x, us, sreg[4]);  sreg[5] = fmaf(k1.y, us, sreg[5]);
                sreg[6] = fmaf(k1.z, us, sreg[6]);  sreg[7] = fmaf(k1.w, us, sreg[7]);
                sreg[8] = fmaf(k2.x, us, sreg[8]);  sreg[9] = fmaf(k2.y, us, sreg[9]);
                sreg[10] = fmaf(k2.z, us, sreg[10]); sreg[11] = fmaf(k2.w, us, sreg[11]);
            }
            const float* ap = AB + t * 12;
            #pragma unroll
            for (int i2 = 0; i2 < 12; i2 += 2) {
                float2 tmp;
                tmp.x = sreg[i2] * ap[i2];
                tmp.y = sreg[i2 + 1] * ap[i2 + 1];
                *(float2*)(sr + i2) = tmp;
            }
        }
        CP_WAIT0();
        __syncthreads();
    }
    #undef CS_ISSUE
}

// ---------------- launch ----------------
extern "C" void kernel_launch(void* const* d_in, const int* in_sizes, int n_in,
                              void* d_out, int out_size) {
    (void)in_sizes; (void)n_in; (void)out_size;
    const float* x         = (const float*)d_in[0];
    const float* wq_a      = (const float*)d_in[3];
    const float* q_norm_w  = (const float*)d_in[4];
    const float* wq_b      = (const float*)d_in[5];
    const float* wkv_a     = (const float*)d_in[6];
    const float* kv_norm_w = (const float*)d_in[7];
    const float* wkv_b     = (const float*)d_in[8];
    const float* wg_w      = (const float*)d_in[9];
    const float* wg_b      = (const float*)d_in[10];
    const float* wb        = (const float*)d_in[11];
    const float* wo        = (const float*)d_in[12];
    float* out = (float*)d_out;

    float *bc, *big, *qn, *kvn, *q, *kv, *kf, *ov;
    float *wch, *kch, *qch, *a16, *Nm, *Gm;
    cudaGetSymbolAddress((void**)&bc,  d_bc);
    cudaGetSymbolAddress((void**)&big, d_big);
    cudaGetSymbolAddress((void**)&qn,  d_qn);
    cudaGetSymbolAddress((void**)&kvn, d_kvn);
    cudaGetSymbolAddress((void**)&q,   d_q);
    cudaGetSymbolAddress((void**)&kv,  d_kv);
    cudaGetSymbolAddress((void**)&kf,  d_kf);
    cudaGetSymbolAddress((void**)&ov,  d_ov);
    cudaGetSymbolAddress((void**)&wch, d_wch);
    cudaGetSymbolAddress((void**)&kch, d_kch);
    cudaGetSymbolAddress((void**)&qch, d_qch);
    cudaGetSymbolAddress((void**)&a16, d_a16);
    cudaGetSymbolAddress((void**)&Nm,  d_Nm);
    cudaGetSymbolAddress((void**)&Gm,  d_Gm);

    static int smem_set = 0;
    if (!smem_set) {
        cudaFuncSetAttribute(chunk_seq, cudaFuncAttributeMaxDynamicSharedMemorySize, CS_BYTES);
        smem_set = 1;
    }

    concat_w<<<dim3(NBIG / 128, DIMX), 128>>>(wq_a, wkv_a, wg_w, wb, bc);

    // Stage 1: big = x @ [wq_a | wkv_a | wg_w | wb] (+ sigmoid epilogues)
    tgemm_kernel<1><<<dim3(NBIG / BN, TT / BM), 256>>>(NBIG, DIMX, x, DIMX, bc, NBIG, wg_b, big, NBIG);

    // Stage 2: fused RMS norms
    rms_fused<<<TT, 256>>>(big, q_norm_w, kv_norm_w, qn, kvn);

    // Stage 3: batched up-projections
    tgemm_dual_kernel<<<dim3(2048 / BN, TT / BM, 2), 256>>>(
        1536, QLR,  qn,  wq_b,  q,
        2048, KVLR, kvn, wkv_b, kv);

    // Stage 4: l2norm q/k, assemble k
    prep_kernel<<<TT * HH, 192>>>(q, kv, big, kf);

    // Stage 5a: chunk prepass
    chunk_pre<<<NCH * HH, 256>>>(q, kf, big, wch, kch, qch, a16, Nm, Gm);

    // Stage 5b: sequential chunk scan (vectorized + cp.async double-buffered)
    chunk_seq<<<HH * 8, 256, CS_BYTES>>>(wch, kch, qch, a16, Nm, Gm, kv, ov);

    // Stage 6: output projection (plain TF32)
    tgemm_kernel<0><<<dim3(DIMX / BN, TT / BM), 256>>>(DIMX, DIMX, ov, DIMX, wo, DIMX, nullptr, out, DIMX);
}